// round 2
// baseline (speedup 1.0000x reference)
#include <cuda_runtime.h>

#define NN 100000
#define NE 3200000
#define FIN 128
#define FOUT 16

// Scratch (no allocations allowed): deg -> overwritten in place by dinv; hs = (xW)*dinv
__device__ float g_deg[NN];
__device__ float g_hs[(size_t)NN * FOUT];
__device__ int g_is64;  // 1 if edge_index is int64, 0 if int32

// Detect edge_index dtype: for int64 (little-endian, values in [0, 1e5)), every
// odd 32-bit word is the zero high-half. For int32 data, odd words are random ids.
__global__ void k_detect(const unsigned int* __restrict__ ei32) {
    if (threadIdx.x == 0 && blockIdx.x == 0) {
        int all_zero = 1;
        for (int k = 0; k < 64; k++) {
            if (ei32[2 * k + 1] != 0u) { all_zero = 0; break; }
        }
        g_is64 = all_zero;
    }
}

__device__ __forceinline__ int load_idx(const void* ei, long long pos64, int pos32, int is64) {
    if (is64) return (int)((const long long*)ei)[pos64];
    return ((const int*)ei)[pos32];
}

__global__ void k_deg_init() {
    int i = blockIdx.x * blockDim.x + threadIdx.x;
    if (i < NN) g_deg[i] = 1.0f;  // self-loop weight
}

__global__ void k_deg_acc(const void* __restrict__ ei, const float* __restrict__ ew) {
    int e = blockIdx.x * blockDim.x + threadIdx.x;
    if (e >= NE) return;
    int is64 = g_is64;
    int c = load_idx(ei, (long long)NE + e, NE + e, is64);  // col (destination)
    atomicAdd(&g_deg[c], ew[e]);
}

__global__ void k_dinv() {
    int i = blockIdx.x * blockDim.x + threadIdx.x;
    if (i < NN) g_deg[i] = rsqrtf(g_deg[i]);  // deg >= 1 always
}

// hs[node] = (x[node] @ W) * dinv[node]; out[node] initialized to hs[node] (self-loop term)
__global__ void __launch_bounds__(256) k_gemm(const float* __restrict__ x,
                                              const float* __restrict__ W,
                                              float* __restrict__ out) {
    __shared__ float4 Ws[FIN * FOUT / 4];  // 8KB, [k][f] layout
    for (int i = threadIdx.x; i < FIN * FOUT / 4; i += 256)
        Ws[i] = ((const float4*)W)[i];
    __syncthreads();

    int node = blockIdx.x * 256 + threadIdx.x;
    if (node >= NN) return;

    const float4* xr = (const float4*)(x + (size_t)node * FIN);
    float acc[FOUT];
#pragma unroll
    for (int f = 0; f < FOUT; f++) acc[f] = 0.0f;

#pragma unroll 4
    for (int k4 = 0; k4 < FIN / 4; k4++) {
        float4 xv = xr[k4];
#pragma unroll
        for (int j = 0; j < 4; j++) {
            float xs = (j == 0) ? xv.x : (j == 1) ? xv.y : (j == 2) ? xv.z : xv.w;
            int k = k4 * 4 + j;
#pragma unroll
            for (int q = 0; q < 4; q++) {
                float4 w = Ws[k * 4 + q];
                acc[q * 4 + 0] += xs * w.x;
                acc[q * 4 + 1] += xs * w.y;
                acc[q * 4 + 2] += xs * w.z;
                acc[q * 4 + 3] += xs * w.w;
            }
        }
    }

    float di = g_deg[node];  // holds dinv now
    float4* hs4 = (float4*)(g_hs + (size_t)node * FOUT);
    float4* o4 = (float4*)(out + (size_t)node * FOUT);
#pragma unroll
    for (int q = 0; q < 4; q++) {
        float4 v = make_float4(acc[q * 4 + 0] * di, acc[q * 4 + 1] * di,
                               acc[q * 4 + 2] * di, acc[q * 4 + 3] * di);
        hs4[q] = v;
        o4[q] = v;
    }
}

// out[col] += hs[row] * w  via vector atomics (4x red.global.add.v4.f32 per edge)
__global__ void k_scatter(const void* __restrict__ ei, const float* __restrict__ ew,
                          float* __restrict__ out) {
    int e = blockIdx.x * blockDim.x + threadIdx.x;
    if (e >= NE) return;
    int is64 = g_is64;
    int r = load_idx(ei, e, e, is64);
    int c = load_idx(ei, (long long)NE + e, NE + e, is64);
    float w = ew[e];
    const float4* h4 = (const float4*)(g_hs + (size_t)r * FOUT);
    float* dst = out + (size_t)c * FOUT;
#pragma unroll
    for (int q = 0; q < 4; q++) {
        float4 m = h4[q];
        asm volatile("red.global.add.v4.f32 [%0], {%1, %2, %3, %4};"
                     :: "l"(dst + q * 4), "f"(m.x * w), "f"(m.y * w), "f"(m.z * w), "f"(m.w * w)
                     : "memory");
    }
}

// out = out * dinv[node] + b
__global__ void k_final(float* __restrict__ out, const float* __restrict__ b) {
    int i = blockIdx.x * blockDim.x + threadIdx.x;
    if (i >= NN * 4) return;  // one float4 per thread
    int node = i >> 2;
    int q = i & 3;
    float di = g_deg[node];
    float4 bv = ((const float4*)b)[q];
    float4 o = ((float4*)out)[i];
    o.x = o.x * di + bv.x;
    o.y = o.y * di + bv.y;
    o.z = o.z * di + bv.z;
    o.w = o.w * di + bv.w;
    ((float4*)out)[i] = o;
}

extern "C" void kernel_launch(void* const* d_in, const int* in_sizes, int n_in,
                              void* d_out, int out_size) {
    const float* x = (const float*)d_in[0];
    const void* ei = d_in[1];
    const float* ew = (const float*)d_in[2];
    const float* W = (const float*)d_in[3];
    const float* b = (const float*)d_in[4];
    float* out = (float*)d_out;

    k_detect<<<1, 32>>>((const unsigned int*)ei);
    k_deg_init<<<(NN + 255) / 256, 256>>>();
    k_deg_acc<<<(NE + 255) / 256, 256>>>(ei, ew);
    k_dinv<<<(NN + 255) / 256, 256>>>();
    k_gemm<<<(NN + 255) / 256, 256>>>(x, W, out);
    k_scatter<<<(NE + 255) / 256, 256>>>(ei, ew, out);
    k_final<<<(NN * 4 + 255) / 256, 256>>>(out, b);
}